// round 1
// baseline (speedup 1.0000x reference)
#include <cuda_runtime.h>
#include <cuda_bf16.h>
#include <math.h>

#define IN_DIM 256
#define HID    128
#define EPS_C  0.3f
#define MAXN   100000

// -------- scratch (static device globals; no allocation) --------
__device__ float  g_h[(size_t)MAXN * HID];   // h = relu(x@w1.T+b1)
__device__ float4 g_p[MAXN];                 // per-node (a_dst, a_src, norm, 0)
__device__ int    g_deg[MAXN];               // in-degree of dst

// ---------------------------------------------------------------
// K0: zero degree array
__global__ void k_zero_deg(int n) {
    int i = blockIdx.x * blockDim.x + threadIdx.x;
    if (i < n) g_deg[i] = 0;
}

// K1: degree histogram over dst
__global__ void k_deg(const int* __restrict__ dst, int E) {
    int i = blockIdx.x * blockDim.x + threadIdx.x;
    if (i < E) atomicAdd(&g_deg[dst[i]], 1);
}

// ---------------------------------------------------------------
// K2: GEMM  h[n, j] = relu( sum_k x[n,k] * w1[j,k] + b1[j] ),  out = EPS*h
// BM=BN=128, BK=16, 256 threads, 8x8 micro-tile per thread.
__global__ __launch_bounds__(256) void k_gemm(
    const float* __restrict__ x, const float* __restrict__ w1,
    const float* __restrict__ b1, float* __restrict__ out, int Nn)
{
    const int BM = 128, BN = 128, BK = 16;
    __shared__ float xs[BK][BM];
    __shared__ float ws[BK][BN];

    int row0 = blockIdx.x * BM;
    int tx = threadIdx.x & 15;        // 0..15 -> col group
    int ty = threadIdx.x >> 4;        // 0..15 -> row group

    float acc[8][8];
#pragma unroll
    for (int i = 0; i < 8; i++)
#pragma unroll
        for (int j = 0; j < 8; j++) acc[i][j] = 0.0f;

    for (int k0 = 0; k0 < IN_DIM; k0 += BK) {
        // load x tile (128 rows x 16 k), 2 float4 per thread, transposed store
#pragma unroll
        for (int l = 0; l < 2; l++) {
            int lin = threadIdx.x * 2 + l;       // 0..511
            int r   = lin >> 2;                  // 0..127
            int kv  = lin & 3;                   // float4 index within 16
            float4 v = make_float4(0.f, 0.f, 0.f, 0.f);
            int gr = row0 + r;
            if (gr < Nn)
                v = *(const float4*)(x + (size_t)gr * IN_DIM + k0 + kv * 4);
            xs[kv * 4 + 0][r] = v.x;
            xs[kv * 4 + 1][r] = v.y;
            xs[kv * 4 + 2][r] = v.z;
            xs[kv * 4 + 3][r] = v.w;
        }
        // load w tile (128 cols x 16 k), transposed store
#pragma unroll
        for (int l = 0; l < 2; l++) {
            int lin = threadIdx.x * 2 + l;
            int r   = lin >> 2;                  // output col j
            int kv  = lin & 3;
            float4 v = *(const float4*)(w1 + (size_t)r * IN_DIM + k0 + kv * 4);
            ws[kv * 4 + 0][r] = v.x;
            ws[kv * 4 + 1][r] = v.y;
            ws[kv * 4 + 2][r] = v.z;
            ws[kv * 4 + 3][r] = v.w;
        }
        __syncthreads();

#pragma unroll
        for (int k = 0; k < BK; k++) {
            float a[8], b[8];
#pragma unroll
            for (int i = 0; i < 8; i++) a[i] = xs[k][ty * 8 + i];
#pragma unroll
            for (int j = 0; j < 8; j++) b[j] = ws[k][tx * 8 + j];
#pragma unroll
            for (int i = 0; i < 8; i++)
#pragma unroll
                for (int j = 0; j < 8; j++) acc[i][j] += a[i] * b[j];
        }
        __syncthreads();
    }

    // epilogue: + bias, relu, write h and out = EPS*h
    float bb[8];
#pragma unroll
    for (int j = 0; j < 8; j++) bb[j] = b1[tx * 8 + j];

#pragma unroll
    for (int i = 0; i < 8; i++) {
        int r = row0 + ty * 8 + i;
        if (r >= Nn) break;
        float hv[8];
#pragma unroll
        for (int j = 0; j < 8; j++) {
            float t = acc[i][j] + bb[j];
            hv[j] = t > 0.0f ? t : 0.0f;
        }
        float* hp = g_h + (size_t)r * HID + tx * 8;
        float* op = out + (size_t)r * HID + tx * 8;
        *(float4*)(hp + 0) = make_float4(hv[0], hv[1], hv[2], hv[3]);
        *(float4*)(hp + 4) = make_float4(hv[4], hv[5], hv[6], hv[7]);
        *(float4*)(op + 0) = make_float4(EPS_C * hv[0], EPS_C * hv[1], EPS_C * hv[2], EPS_C * hv[3]);
        *(float4*)(op + 4) = make_float4(EPS_C * hv[4], EPS_C * hv[5], EPS_C * hv[6], EPS_C * hv[7]);
    }
}

// ---------------------------------------------------------------
// K3: per-node params: a_dst = h.wd, a_src = h.ws, norm = rsqrt(max(deg,1))
// one warp per node
__global__ __launch_bounds__(256) void k_params(
    const float* __restrict__ gate_w, int Nn)
{
    int warp = (blockIdx.x * blockDim.x + threadIdx.x) >> 5;
    int lane = threadIdx.x & 31;
    if (warp >= Nn) return;

    const float4* h4 = (const float4*)(g_h + (size_t)warp * HID);
    const float4* g4 = (const float4*)gate_w;
    float4 hv = h4[lane];
    float4 wd = g4[lane];
    float4 wsv = g4[32 + lane];
    float pd = hv.x * wd.x + hv.y * wd.y + hv.z * wd.z + hv.w * wd.w;
    float ps = hv.x * wsv.x + hv.y * wsv.y + hv.z * wsv.z + hv.w * wsv.w;
#pragma unroll
    for (int off = 16; off > 0; off >>= 1) {
        pd += __shfl_down_sync(0xffffffffu, pd, off);
        ps += __shfl_down_sync(0xffffffffu, ps, off);
    }
    if (lane == 0) {
        float d = (float)g_deg[warp];
        if (d < 1.0f) d = 1.0f;
        g_p[warp] = make_float4(pd, ps, rsqrtf(d), 0.0f);
    }
}

// ---------------------------------------------------------------
// K4: edge scatter. One warp per edge: compute gate once (lane 0),
// broadcast, then 32 lanes do vectorized gather + red.add.v4.f32 scatter.
__global__ __launch_bounds__(256) void k_edges(
    const int* __restrict__ ei, const float* __restrict__ gate_b,
    float* __restrict__ out, int E)
{
    int warp = blockIdx.x * (blockDim.x >> 5) + (threadIdx.x >> 5);
    int lane = threadIdx.x & 31;
    if (warp >= E) return;

    int src = 0, dst = 0;
    float e = 0.0f;
    if (lane == 0) {
        src = ei[warp];
        dst = ei[E + warp];
        float4 pd = g_p[dst];
        float4 ps = g_p[src];
        float g = tanhf(pd.x + ps.y + gate_b[0]);
        e = g * pd.z * ps.z;
    }
    src = __shfl_sync(0xffffffffu, src, 0);
    dst = __shfl_sync(0xffffffffu, dst, 0);
    e   = __shfl_sync(0xffffffffu, e, 0);

    float4 v = ((const float4*)(g_h + (size_t)src * HID))[lane];
    float* op = out + (size_t)dst * HID + lane * 4;
    asm volatile(
        "red.global.add.v4.f32 [%0], {%1, %2, %3, %4};"
        :: "l"(op), "f"(v.x * e), "f"(v.y * e), "f"(v.z * e), "f"(v.w * e)
        : "memory");
}

// ---------------------------------------------------------------
extern "C" void kernel_launch(void* const* d_in, const int* in_sizes, int n_in,
                              void* d_out, int out_size)
{
    const float* x      = (const float*)d_in[0];
    const int*   ei     = (const int*)d_in[1];
    const float* w1     = (const float*)d_in[2];
    const float* b1     = (const float*)d_in[3];
    const float* gate_w = (const float*)d_in[4];
    const float* gate_b = (const float*)d_in[5];
    float* out = (float*)d_out;

    int Nn = in_sizes[0] / IN_DIM;     // 100000
    int E  = in_sizes[1] / 2;          // 1600000

    // degree
    k_zero_deg<<<(Nn + 255) / 256, 256>>>(Nn);
    k_deg<<<(E + 255) / 256, 256>>>(ei + E, E);

    // h + out = EPS*h
    k_gemm<<<(Nn + 127) / 128, 256>>>(x, w1, b1, out, Nn);

    // per-node params (8 warps / block)
    k_params<<<(Nn + 7) / 8, 256>>>(gate_w, Nn);

    // edge scatter (8 warps / block)
    k_edges<<<(E + 7) / 8, 256>>>(ei, gate_b, out, E);
}

// round 3
// speedup vs baseline: 1.2852x; 1.2852x over previous
#include <cuda_runtime.h>
#include <cuda_bf16.h>
#include <math.h>

#define IN_DIM 256
#define HID    128
#define EPS_C  0.3f
#define MAXN   100000
#define MAXE   1600000

// -------- scratch (static device globals; no allocation) --------
__device__ float  g_h[(size_t)MAXN * HID];   // h = relu(x@w1.T+b1)
__device__ float4 g_p[MAXN];                 // per-node (a_dst, a_src, norm, 0)
__device__ int    g_deg[MAXN];               // in-degree of dst
__device__ int    g_off[MAXN];               // CSR row offsets (exclusive scan of deg)
__device__ int    g_cur[MAXN];               // fill cursors
__device__ int    g_bsum[512];
__device__ int    g_bscan[512];
__device__ float2 g_csr[MAXE];               // per-edge (e, src_bits) sorted by dst

// ---------------------------------------------------------------
__global__ void k_zero(int n) {
    int i = blockIdx.x * blockDim.x + threadIdx.x;
    if (i < n) { g_deg[i] = 0; g_cur[i] = 0; }
}

__global__ void k_deg(const int* __restrict__ dst, int E) {
    int i = blockIdx.x * blockDim.x + threadIdx.x;
    if (i < E) atomicAdd(&g_deg[dst[i]], 1);
}

// ---------------------------------------------------------------
// Exclusive scan of g_deg -> g_off (3 small kernels; N <= 131072)
__global__ void k_scan1(int n) {
    __shared__ int s[256];
    int t = threadIdx.x, i = blockIdx.x * 256 + t;
    int v = (i < n) ? g_deg[i] : 0;
    s[t] = v; __syncthreads();
#pragma unroll
    for (int o = 1; o < 256; o <<= 1) {
        int x = (t >= o) ? s[t - o] : 0;
        __syncthreads();
        s[t] += x;
        __syncthreads();
    }
    if (i < n) g_off[i] = s[t] - v;
    if (t == 255) g_bsum[blockIdx.x] = s[255];
}
__global__ void k_scan2(int nb) {
    __shared__ int s[512];
    int t = threadIdx.x;
    int v = (t < nb) ? g_bsum[t] : 0;
    s[t] = v; __syncthreads();
#pragma unroll
    for (int o = 1; o < 512; o <<= 1) {
        int x = (t >= o) ? s[t - o] : 0;
        __syncthreads();
        s[t] += x;
        __syncthreads();
    }
    if (t < nb) g_bscan[t] = s[t] - v;
}
__global__ void k_scan3(int n) {
    int i = blockIdx.x * blockDim.x + threadIdx.x;
    if (i < n) g_off[i] += g_bscan[i >> 8];
}

// ---------------------------------------------------------------
// GEMM  h[n, j] = relu( sum_k x[n,k] * w1[j,k] + b1[j] )
// BM=BN=128, BK=16, 256 threads, 8x8 micro-tile, packed fma.rn.f32x2.
// xs2: x values duplicated  -> a2[i] loads need no packing (broadcast).
// ws3: w cols swizzled (p*32 + tx*2 + q) -> b2[p] loads conflict-free pairs.
#define FMA2(d, a, b, c) \
    asm("fma.rn.f32x2 %0, %1, %2, %3;" : "=l"(d) : "l"(a), "l"(b), "l"(c))

__global__ __launch_bounds__(256, 2) void k_gemm(
    const float* __restrict__ x, const float* __restrict__ w1,
    const float* __restrict__ b1, int Nn)
{
    const int BM = 128, BK = 16;
    __shared__ float xs2[BK][2 * BM];   // [k][2r]=[k][2r+1]=x[row0+r][k]
    __shared__ float ws3[BK][128];      // [k][p*32+t*2+q] = w1[t*8+2p+q][k]

    int row0 = blockIdx.x * BM;
    int tx = threadIdx.x & 15;
    int ty = threadIdx.x >> 4;

    unsigned long long acc2[8][4];
#pragma unroll
    for (int i = 0; i < 8; i++)
#pragma unroll
        for (int p = 0; p < 4; p++) acc2[i][p] = 0ull;

    for (int k0 = 0; k0 < IN_DIM; k0 += BK) {
#pragma unroll
        for (int l = 0; l < 2; l++) {
            int lin = threadIdx.x * 2 + l;   // 0..511
            int r   = lin >> 2;              // 0..127
            int kv  = lin & 3;
            float4 v = make_float4(0.f, 0.f, 0.f, 0.f);
            int gr = row0 + r;
            if (gr < Nn)
                v = *(const float4*)(x + (size_t)gr * IN_DIM + k0 + kv * 4);
            *(float2*)&xs2[kv * 4 + 0][2 * r] = make_float2(v.x, v.x);
            *(float2*)&xs2[kv * 4 + 1][2 * r] = make_float2(v.y, v.y);
            *(float2*)&xs2[kv * 4 + 2][2 * r] = make_float2(v.z, v.z);
            *(float2*)&xs2[kv * 4 + 3][2 * r] = make_float2(v.w, v.w);
        }
#pragma unroll
        for (int l = 0; l < 2; l++) {
            int lin = threadIdx.x * 2 + l;
            int col = lin >> 2;              // 0..127 output col
            int kv  = lin & 3;
            float4 v = *(const float4*)(w1 + (size_t)col * IN_DIM + k0 + kv * 4);
            int t = col >> 3, p = (col & 7) >> 1, q = col & 1;
            int nc = p * 32 + t * 2 + q;
            ws3[kv * 4 + 0][nc] = v.x;
            ws3[kv * 4 + 1][nc] = v.y;
            ws3[kv * 4 + 2][nc] = v.z;
            ws3[kv * 4 + 3][nc] = v.w;
        }
        __syncthreads();

#pragma unroll
        for (int k = 0; k < BK; k++) {
            unsigned long long a2[8], b2[4];
#pragma unroll
            for (int i = 0; i < 8; i++)
                a2[i] = *(const unsigned long long*)&xs2[k][2 * (ty * 8 + i)];
#pragma unroll
            for (int p = 0; p < 4; p++)
                b2[p] = *(const unsigned long long*)&ws3[k][p * 32 + tx * 2];
#pragma unroll
            for (int i = 0; i < 8; i++)
#pragma unroll
                for (int p = 0; p < 4; p++)
                    FMA2(acc2[i][p], a2[i], b2[p], acc2[i][p]);
        }
        __syncthreads();
    }

    float bb[8];
#pragma unroll
    for (int j = 0; j < 8; j++) bb[j] = b1[tx * 8 + j];

#pragma unroll
    for (int i = 0; i < 8; i++) {
        int r = row0 + ty * 8 + i;
        if (r >= Nn) break;
        float hv[8];
#pragma unroll
        for (int p = 0; p < 4; p++) {
            union { unsigned long long u; float2 f; } cv;
            cv.u = acc2[i][p];
            hv[2 * p + 0] = cv.f.x;
            hv[2 * p + 1] = cv.f.y;
        }
#pragma unroll
        for (int j = 0; j < 8; j++) {
            float t = hv[j] + bb[j];
            hv[j] = t > 0.0f ? t : 0.0f;
        }
        float* hp = g_h + (size_t)r * HID + tx * 8;
        *(float4*)(hp + 0) = make_float4(hv[0], hv[1], hv[2], hv[3]);
        *(float4*)(hp + 4) = make_float4(hv[4], hv[5], hv[6], hv[7]);
    }
}

// ---------------------------------------------------------------
// per-node params: a_dst = h.wd, a_src = h.ws, norm = rsqrt(max(deg,1))
__global__ __launch_bounds__(256) void k_params(
    const float* __restrict__ gate_w, int Nn)
{
    int warp = (blockIdx.x * blockDim.x + threadIdx.x) >> 5;
    int lane = threadIdx.x & 31;
    if (warp >= Nn) return;

    const float4* h4 = (const float4*)(g_h + (size_t)warp * HID);
    const float4* g4 = (const float4*)gate_w;
    float4 hv = h4[lane];
    float4 wd = g4[lane];
    float4 wsv = g4[32 + lane];
    float pd = hv.x * wd.x + hv.y * wd.y + hv.z * wd.z + hv.w * wd.w;
    float ps = hv.x * wsv.x + hv.y * wsv.y + hv.z * wsv.z + hv.w * wsv.w;
#pragma unroll
    for (int off = 16; off > 0; off >>= 1) {
        pd += __shfl_down_sync(0xffffffffu, pd, off);
        ps += __shfl_down_sync(0xffffffffu, ps, off);
    }
    if (lane == 0) {
        float d = (float)g_deg[warp];
        if (d < 1.0f) d = 1.0f;
        g_p[warp] = make_float4(pd, ps, rsqrtf(d), 0.0f);
    }
}

// ---------------------------------------------------------------
// fill CSR: one thread per edge; compute gate e, place (e, src) by dst bucket
__global__ void k_fill(const int* __restrict__ ei,
                       const float* __restrict__ gate_b, int E)
{
    int i = blockIdx.x * blockDim.x + threadIdx.x;
    if (i >= E) return;
    int s = ei[i];
    int d = ei[E + i];
    float4 pd = g_p[d];
    float4 ps = g_p[s];
    float g = tanhf(pd.x + ps.y + gate_b[0]);
    float e = g * pd.z * ps.z;
    int pos = g_off[d] + atomicAdd(&g_cur[d], 1);
    g_csr[pos] = make_float2(e, __int_as_float(s));
}

// ---------------------------------------------------------------
// aggregate: one warp per dst node; no atomics; fuse out = EPS*h + z.
// 2 edges per iteration with independent accumulators -> 2x gather MLP.
__global__ __launch_bounds__(256) void k_agg(float* __restrict__ out, int Nn)
{
    int node = blockIdx.x * 8 + (threadIdx.x >> 5);
    int lane = threadIdx.x & 31;
    if (node >= Nn) return;

    int beg = g_off[node];
    int end = beg + g_deg[node];

    float4 acc0 = make_float4(0.f, 0.f, 0.f, 0.f);
    float4 acc1 = make_float4(0.f, 0.f, 0.f, 0.f);

    int t = beg;
    for (; t + 1 < end; t += 2) {
        float2 c0 = g_csr[t];
        float2 c1 = g_csr[t + 1];
        int s0 = __float_as_int(c0.y);
        int s1 = __float_as_int(c1.y);
        float4 h0 = ((const float4*)(g_h + (size_t)s0 * HID))[lane];
        float4 h1 = ((const float4*)(g_h + (size_t)s1 * HID))[lane];
        acc0.x += h0.x * c0.x; acc0.y += h0.y * c0.x;
        acc0.z += h0.z * c0.x; acc0.w += h0.w * c0.x;
        acc1.x += h1.x * c1.x; acc1.y += h1.y * c1.x;
        acc1.z += h1.z * c1.x; acc1.w += h1.w * c1.x;
    }
    if (t < end) {
        float2 c0 = g_csr[t];
        int s0 = __float_as_int(c0.y);
        float4 h0 = ((const float4*)(g_h + (size_t)s0 * HID))[lane];
        acc0.x += h0.x * c0.x; acc0.y += h0.y * c0.x;
        acc0.z += h0.z * c0.x; acc0.w += h0.w * c0.x;
    }

    float4 mine = ((const float4*)(g_h + (size_t)node * HID))[lane];
    float4 o;
    o.x = EPS_C * mine.x + acc0.x + acc1.x;
    o.y = EPS_C * mine.y + acc0.y + acc1.y;
    o.z = EPS_C * mine.z + acc0.z + acc1.z;
    o.w = EPS_C * mine.w + acc0.w + acc1.w;
    ((float4*)(out + (size_t)node * HID))[lane] = o;
}

// ---------------------------------------------------------------
extern "C" void kernel_launch(void* const* d_in, const int* in_sizes, int n_in,
                              void* d_out, int out_size)
{
    const float* x      = (const float*)d_in[0];
    const int*   ei     = (const int*)d_in[1];
    const float* w1     = (const float*)d_in[2];
    const float* b1     = (const float*)d_in[3];
    const float* gate_w = (const float*)d_in[4];
    const float* gate_b = (const float*)d_in[5];
    float* out = (float*)d_out;

    int Nn = in_sizes[0] / IN_DIM;     // 100000
    int E  = in_sizes[1] / 2;          // 1600000
    int nb = (Nn + 255) / 256;         // scan blocks (391)

    k_zero<<<(Nn + 255) / 256, 256>>>(Nn);
    k_deg<<<(E + 255) / 256, 256>>>(ei + E, E);

    k_scan1<<<nb, 256>>>(Nn);
    k_scan2<<<1, 512>>>(nb);
    k_scan3<<<(Nn + 255) / 256, 256>>>(Nn);

    k_gemm<<<(Nn + 127) / 128, 256>>>(x, w1, b1, Nn);
    k_params<<<(Nn + 7) / 8, 256>>>(gate_w, Nn);

    k_fill<<<(E + 255) / 256, 256>>>(ei, gate_b, E);
    k_agg<<<(Nn + 7) / 8, 256>>>(out, Nn);
}

// round 4
// speedup vs baseline: 1.3389x; 1.0418x over previous
#include <cuda_runtime.h>
#include <cuda_bf16.h>
#include <math.h>

#define IN_DIM 256
#define HID    128
#define EPS_C  0.3f
#define MAXN   100000
#define MAXE   1600000

// -------- scratch (static device globals; no allocation) --------
__device__ float  g_h[(size_t)MAXN * HID];   // h = relu(x@w1.T+b1)
__device__ float4 g_p[MAXN];                 // per-node (a_dst, a_src, norm, 0)
__device__ int    g_deg[MAXN];               // in-degree of dst
__device__ int    g_off[MAXN];               // CSR row offsets (exclusive scan of deg)
__device__ int    g_cur[MAXN];               // fill cursors
__device__ int    g_bsum[512];
__device__ int    g_bscan[512];
__device__ float2 g_csr[MAXE];               // per-edge (e, src_bits) sorted by dst

// ---------------------------------------------------------------
__global__ void k_zero(int n) {
    int i = blockIdx.x * blockDim.x + threadIdx.x;
    if (i < n) { g_deg[i] = 0; g_cur[i] = 0; }
}

__global__ void k_deg(const int* __restrict__ dst, int E) {
    int i = blockIdx.x * blockDim.x + threadIdx.x;
    if (i < E) atomicAdd(&g_deg[dst[i]], 1);
}

// ---------------------------------------------------------------
// Exclusive scan of g_deg -> g_off (3 small kernels; N <= 131072)
__global__ void k_scan1(int n) {
    __shared__ int s[256];
    int t = threadIdx.x, i = blockIdx.x * 256 + t;
    int v = (i < n) ? g_deg[i] : 0;
    s[t] = v; __syncthreads();
#pragma unroll
    for (int o = 1; o < 256; o <<= 1) {
        int x = (t >= o) ? s[t - o] : 0;
        __syncthreads();
        s[t] += x;
        __syncthreads();
    }
    if (i < n) g_off[i] = s[t] - v;
    if (t == 255) g_bsum[blockIdx.x] = s[255];
}
__global__ void k_scan2(int nb) {
    __shared__ int s[512];
    int t = threadIdx.x;
    int v = (t < nb) ? g_bsum[t] : 0;
    s[t] = v; __syncthreads();
#pragma unroll
    for (int o = 1; o < 512; o <<= 1) {
        int x = (t >= o) ? s[t - o] : 0;
        __syncthreads();
        s[t] += x;
        __syncthreads();
    }
    if (t < nb) g_bscan[t] = s[t] - v;
}
__global__ void k_scan3(int n) {
    int i = blockIdx.x * blockDim.x + threadIdx.x;
    if (i < n) g_off[i] += g_bscan[i >> 8];
}

// ---------------------------------------------------------------
// GEMM  h[n, j] = relu( sum_k x[n,k] * w1[j,k] + b1[j] )
// BM=BN=128, BK=16, 256 threads, 8x8 micro-tile, packed fma.rn.f32x2.
// Fused epilogue also computes per-node params:
//   a_dst = h.wd, a_src = h.ws (16-lane shfl reduction), norm = rsqrt(max(deg,1)).
#define FMA2(d, a, b, c) \
    asm("fma.rn.f32x2 %0, %1, %2, %3;" : "=l"(d) : "l"(a), "l"(b), "l"(c))

__global__ __launch_bounds__(256, 2) void k_gemm(
    const float* __restrict__ x, const float* __restrict__ w1,
    const float* __restrict__ b1, const float* __restrict__ gate_w, int Nn)
{
    const int BM = 128, BK = 16;
    __shared__ float xs2[BK][2 * BM];   // [k][2r]=[k][2r+1]=x[row0+r][k]
    __shared__ float ws3[BK][128];      // [k][p*32+t*2+q] = w1[t*8+2p+q][k]

    int row0 = blockIdx.x * BM;
    int tx = threadIdx.x & 15;
    int ty = threadIdx.x >> 4;

    unsigned long long acc2[8][4];
#pragma unroll
    for (int i = 0; i < 8; i++)
#pragma unroll
        for (int p = 0; p < 4; p++) acc2[i][p] = 0ull;

    for (int k0 = 0; k0 < IN_DIM; k0 += BK) {
#pragma unroll
        for (int l = 0; l < 2; l++) {
            int lin = threadIdx.x * 2 + l;   // 0..511
            int r   = lin >> 2;              // 0..127
            int kv  = lin & 3;
            float4 v = make_float4(0.f, 0.f, 0.f, 0.f);
            int gr = row0 + r;
            if (gr < Nn)
                v = *(const float4*)(x + (size_t)gr * IN_DIM + k0 + kv * 4);
            *(float2*)&xs2[kv * 4 + 0][2 * r] = make_float2(v.x, v.x);
            *(float2*)&xs2[kv * 4 + 1][2 * r] = make_float2(v.y, v.y);
            *(float2*)&xs2[kv * 4 + 2][2 * r] = make_float2(v.z, v.z);
            *(float2*)&xs2[kv * 4 + 3][2 * r] = make_float2(v.w, v.w);
        }
#pragma unroll
        for (int l = 0; l < 2; l++) {
            int lin = threadIdx.x * 2 + l;
            int col = lin >> 2;              // 0..127 output col
            int kv  = lin & 3;
            float4 v = *(const float4*)(w1 + (size_t)col * IN_DIM + k0 + kv * 4);
            int t = col >> 3, p = (col & 7) >> 1, q = col & 1;
            int nc = p * 32 + t * 2 + q;
            ws3[kv * 4 + 0][nc] = v.x;
            ws3[kv * 4 + 1][nc] = v.y;
            ws3[kv * 4 + 2][nc] = v.z;
            ws3[kv * 4 + 3][nc] = v.w;
        }
        __syncthreads();

#pragma unroll
        for (int k = 0; k < BK; k++) {
            unsigned long long a2[8], b2[4];
#pragma unroll
            for (int i = 0; i < 8; i++)
                a2[i] = *(const unsigned long long*)&xs2[k][2 * (ty * 8 + i)];
#pragma unroll
            for (int p = 0; p < 4; p++)
                b2[p] = *(const unsigned long long*)&ws3[k][p * 32 + tx * 2];
#pragma unroll
            for (int i = 0; i < 8; i++)
#pragma unroll
                for (int p = 0; p < 4; p++)
                    FMA2(acc2[i][p], a2[i], b2[p], acc2[i][p]);
        }
        __syncthreads();
    }

    // ---- epilogue: bias, relu, write h, fused per-node gate params ----
    float bb[8], wdv[8], wsv[8];
#pragma unroll
    for (int j = 0; j < 8; j++) {
        bb[j]  = b1[tx * 8 + j];
        wdv[j] = gate_w[tx * 8 + j];
        wsv[j] = gate_w[HID + tx * 8 + j];
    }

#pragma unroll
    for (int i = 0; i < 8; i++) {
        int r = row0 + ty * 8 + i;   // NOTE: no break — shuffles below need all lanes
        float hv[8];
#pragma unroll
        for (int p = 0; p < 4; p++) {
            union { unsigned long long u; float2 f; } cv;
            cv.u = acc2[i][p];
            hv[2 * p + 0] = cv.f.x;
            hv[2 * p + 1] = cv.f.y;
        }
        float pd = 0.0f, ps = 0.0f;
#pragma unroll
        for (int j = 0; j < 8; j++) {
            float t = hv[j] + bb[j];
            hv[j] = t > 0.0f ? t : 0.0f;
            pd += hv[j] * wdv[j];
            ps += hv[j] * wsv[j];
        }
        // 16-lane reduction across tx (lanes with same ty share a row)
#pragma unroll
        for (int m = 1; m < 16; m <<= 1) {
            pd += __shfl_xor_sync(0xffffffffu, pd, m);
            ps += __shfl_xor_sync(0xffffffffu, ps, m);
        }
        if (r < Nn) {
            float* hp = g_h + (size_t)r * HID + tx * 8;
            *(float4*)(hp + 0) = make_float4(hv[0], hv[1], hv[2], hv[3]);
            *(float4*)(hp + 4) = make_float4(hv[4], hv[5], hv[6], hv[7]);
            if (tx == 0) {
                float d = (float)g_deg[r];
                if (d < 1.0f) d = 1.0f;
                g_p[r] = make_float4(pd, ps, rsqrtf(d), 0.0f);
            }
        }
    }
}

// ---------------------------------------------------------------
// fill CSR: one thread per edge; compute gate e, place (e, src) by dst bucket
__global__ void k_fill(const int* __restrict__ ei,
                       const float* __restrict__ gate_b, int E)
{
    int i = blockIdx.x * blockDim.x + threadIdx.x;
    if (i >= E) return;
    int s = ei[i];
    int d = ei[E + i];
    float4 pd = g_p[d];
    float4 ps = g_p[s];
    float g = tanhf(pd.x + ps.y + gate_b[0]);
    float e = g * pd.z * ps.z;
    int pos = g_off[d] + atomicAdd(&g_cur[d], 1);
    g_csr[pos] = make_float2(e, __int_as_float(s));
}

// ---------------------------------------------------------------
// aggregate: one warp per dst node; no atomics; fuse out = EPS*h + z.
// 4 edges per iteration with independent accumulators -> 4x gather MLP.
__global__ __launch_bounds__(256) void k_agg(float* __restrict__ out, int Nn)
{
    int node = blockIdx.x * 8 + (threadIdx.x >> 5);
    int lane = threadIdx.x & 31;
    if (node >= Nn) return;

    int beg = g_off[node];
    int end = beg + g_deg[node];

    float4 acc0 = make_float4(0.f, 0.f, 0.f, 0.f);
    float4 acc1 = make_float4(0.f, 0.f, 0.f, 0.f);
    float4 acc2 = make_float4(0.f, 0.f, 0.f, 0.f);
    float4 acc3 = make_float4(0.f, 0.f, 0.f, 0.f);

    int t = beg;
    for (; t + 3 < end; t += 4) {
        float2 c0 = g_csr[t];
        float2 c1 = g_csr[t + 1];
        float2 c2 = g_csr[t + 2];
        float2 c3 = g_csr[t + 3];
        float4 h0 = ((const float4*)(g_h + (size_t)__float_as_int(c0.y) * HID))[lane];
        float4 h1 = ((const float4*)(g_h + (size_t)__float_as_int(c1.y) * HID))[lane];
        float4 h2 = ((const float4*)(g_h + (size_t)__float_as_int(c2.y) * HID))[lane];
        float4 h3 = ((const float4*)(g_h + (size_t)__float_as_int(c3.y) * HID))[lane];
        acc0.x += h0.x * c0.x; acc0.y += h0.y * c0.x; acc0.z += h0.z * c0.x; acc0.w += h0.w * c0.x;
        acc1.x += h1.x * c1.x; acc1.y += h1.y * c1.x; acc1.z += h1.z * c1.x; acc1.w += h1.w * c1.x;
        acc2.x += h2.x * c2.x; acc2.y += h2.y * c2.x; acc2.z += h2.z * c2.x; acc2.w += h2.w * c2.x;
        acc3.x += h3.x * c3.x; acc3.y += h3.y * c3.x; acc3.z += h3.z * c3.x; acc3.w += h3.w * c3.x;
    }
    for (; t < end; t++) {
        float2 c0 = g_csr[t];
        float4 h0 = ((const float4*)(g_h + (size_t)__float_as_int(c0.y) * HID))[lane];
        acc0.x += h0.x * c0.x; acc0.y += h0.y * c0.x; acc0.z += h0.z * c0.x; acc0.w += h0.w * c0.x;
    }

    float4 mine = ((const float4*)(g_h + (size_t)node * HID))[lane];
    float4 o;
    o.x = EPS_C * mine.x + ((acc0.x + acc1.x) + (acc2.x + acc3.x));
    o.y = EPS_C * mine.y + ((acc0.y + acc1.y) + (acc2.y + acc3.y));
    o.z = EPS_C * mine.z + ((acc0.z + acc1.z) + (acc2.z + acc3.z));
    o.w = EPS_C * mine.w + ((acc0.w + acc1.w) + (acc2.w + acc3.w));
    ((float4*)(out + (size_t)node * HID))[lane] = o;
}

// ---------------------------------------------------------------
extern "C" void kernel_launch(void* const* d_in, const int* in_sizes, int n_in,
                              void* d_out, int out_size)
{
    const float* x      = (const float*)d_in[0];
    const int*   ei     = (const int*)d_in[1];
    const float* w1     = (const float*)d_in[2];
    const float* b1     = (const float*)d_in[3];
    const float* gate_w = (const float*)d_in[4];
    const float* gate_b = (const float*)d_in[5];
    float* out = (float*)d_out;

    int Nn = in_sizes[0] / IN_DIM;     // 100000
    int E  = in_sizes[1] / 2;          // 1600000
    int nb = (Nn + 255) / 256;         // scan blocks (391)

    // Launch order arranged so k_gemm is the 4th launch (ncu -s 5 -c 1
    // has consistently captured launch #4).
    k_zero<<<(Nn + 255) / 256, 256>>>(Nn);                 // 1
    k_deg<<<(E + 255) / 256, 256>>>(ei + E, E);            // 2
    k_scan1<<<nb, 256>>>(Nn);                              // 3
    k_gemm<<<(Nn + 127) / 128, 256>>>(x, w1, b1, gate_w, Nn); // 4 <- profiled
    k_scan2<<<1, 512>>>(nb);                               // 5
    k_scan3<<<(Nn + 255) / 256, 256>>>(Nn);                // 6
    k_fill<<<(E + 255) / 256, 256>>>(ei, gate_b, E);       // 7
    k_agg<<<(Nn + 7) / 8, 256>>>(out, Nn);                 // 8
}

// round 5
// speedup vs baseline: 1.3470x; 1.0060x over previous
#include <cuda_runtime.h>
#include <cuda_bf16.h>
#include <math.h>

#define IN_DIM 256
#define HID    128
#define EPS_C  0.3f
#define MAXN   100000
#define MAXE   1600000

// -------- scratch (static device globals; no allocation) --------
__device__ float  g_h[(size_t)MAXN * HID];   // h = relu(x@w1.T+b1)
__device__ float4 g_p[MAXN];                 // per-node (a_dst, a_src, norm, 0)
__device__ int    g_deg[MAXN];               // in-degree of dst
__device__ int    g_off[MAXN];               // CSR row offsets (exclusive scan of deg)
__device__ int    g_cur[MAXN];               // fill cursors
__device__ int    g_bsum[512];
__device__ int    g_bscan[512];
__device__ float2 g_csr[MAXE];               // per-edge (e, src_bits) sorted by dst

// ---------------------------------------------------------------
__global__ void k_zero(int n) {
    int i = blockIdx.x * blockDim.x + threadIdx.x;
    if (i < n) { g_deg[i] = 0; g_cur[i] = 0; }
}

__global__ void k_deg(const int* __restrict__ dst, int E) {
    int i = blockIdx.x * blockDim.x + threadIdx.x;
    if (i < E) atomicAdd(&g_deg[dst[i]], 1);
}

// ---------------------------------------------------------------
// Exclusive scan of g_deg -> g_off (3 small kernels; N <= 131072)
__global__ void k_scan1(int n) {
    __shared__ int s[256];
    int t = threadIdx.x, i = blockIdx.x * 256 + t;
    int v = (i < n) ? g_deg[i] : 0;
    s[t] = v; __syncthreads();
#pragma unroll
    for (int o = 1; o < 256; o <<= 1) {
        int x = (t >= o) ? s[t - o] : 0;
        __syncthreads();
        s[t] += x;
        __syncthreads();
    }
    if (i < n) g_off[i] = s[t] - v;
    if (t == 255) g_bsum[blockIdx.x] = s[255];
}
__global__ void k_scan2(int nb) {
    __shared__ int s[512];
    int t = threadIdx.x;
    int v = (t < nb) ? g_bsum[t] : 0;
    s[t] = v; __syncthreads();
#pragma unroll
    for (int o = 1; o < 512; o <<= 1) {
        int x = (t >= o) ? s[t - o] : 0;
        __syncthreads();
        s[t] += x;
        __syncthreads();
    }
    if (t < nb) g_bscan[t] = s[t] - v;
}
__global__ void k_scan3(int n) {
    int i = blockIdx.x * blockDim.x + threadIdx.x;
    if (i < n) g_off[i] += g_bscan[i >> 8];
}

// ---------------------------------------------------------------
// GEMM  h[n, j] = relu( sum_k x[n,k] * w1[j,k] + b1[j] )
// BM=BN=128, BK=16, 256 threads, 8x8 micro-tile, packed fma.rn.f32x2.
// 6 LDS.128 per k (4 for a via duplicated xs2, 2 for b via pair-grouped ws).
// Register-level double buffering of global loads across k0 tiles.
// Fused epilogue computes per-node gate params.
#define FMA2(d, a, b, c) \
    asm("fma.rn.f32x2 %0, %1, %2, %3;" : "=l"(d) : "l"(a), "l"(b), "l"(c))

__global__ __launch_bounds__(256, 2) void k_gemm(
    const float* __restrict__ x, const float* __restrict__ w1,
    const float* __restrict__ b1, const float* __restrict__ gate_w, int Nn)
{
    const int BM = 128, BK = 16;
    __shared__ float xs2[BK][2 * BM];   // [k][2r]=[k][2r+1]=x[row0+r][k]
    __shared__ float wsn[BK][128];      // [k][(p>>1)*64 + t*4 + (p&1)*2 + q] = w1[t*8+2p+q][k]

    int row0 = blockIdx.x * BM;
    int tx = threadIdx.x & 15;
    int ty = threadIdx.x >> 4;

    // addressing for the cooperative loads (same for x and w tiles)
    int lin0 = threadIdx.x * 2;
    int xr   = lin0 >> 2;          // 0..127 row (x) / col (w)
    int xkv0 = lin0 & 3;           // float4 index within 16-k for l=0
    // l=1 has same row, kv+1 (since lin0 is even, lin0&3 in {0,2})
    int wt = xr >> 3, wp0 = (xr & 7) >> 1, wq = xr & 1;
    int wcolbase = (wp0 >> 1) * 64 + wt * 4 + (wp0 & 1) * 2 + wq;
    const float* xrow = x + (size_t)(row0 + xr) * IN_DIM;
    const float* wrow = w1 + (size_t)xr * IN_DIM;
    bool xok = (row0 + xr) < Nn;

    unsigned long long acc2[8][4];
#pragma unroll
    for (int i = 0; i < 8; i++)
#pragma unroll
        for (int p = 0; p < 4; p++) acc2[i][p] = 0ull;

    // prologue: load tile 0
    float4 pxa = make_float4(0.f,0.f,0.f,0.f), pxb = make_float4(0.f,0.f,0.f,0.f);
    float4 pwa, pwb;
    if (xok) {
        pxa = *(const float4*)(xrow + (xkv0 + 0) * 4);
        pxb = *(const float4*)(xrow + (xkv0 + 1) * 4);
    }
    pwa = *(const float4*)(wrow + (xkv0 + 0) * 4);
    pwb = *(const float4*)(wrow + (xkv0 + 1) * 4);

    const int NT = IN_DIM / BK;    // 16 tiles
    for (int kt = 0; kt < NT; kt++) {
        // store prefetched tile to smem
        {
            *(float2*)&xs2[xkv0 * 4 + 0][2 * xr] = make_float2(pxa.x, pxa.x);
            *(float2*)&xs2[xkv0 * 4 + 1][2 * xr] = make_float2(pxa.y, pxa.y);
            *(float2*)&xs2[xkv0 * 4 + 2][2 * xr] = make_float2(pxa.z, pxa.z);
            *(float2*)&xs2[xkv0 * 4 + 3][2 * xr] = make_float2(pxa.w, pxa.w);
            *(float2*)&xs2[xkv0 * 4 + 4][2 * xr] = make_float2(pxb.x, pxb.x);
            *(float2*)&xs2[xkv0 * 4 + 5][2 * xr] = make_float2(pxb.y, pxb.y);
            *(float2*)&xs2[xkv0 * 4 + 6][2 * xr] = make_float2(pxb.z, pxb.z);
            *(float2*)&xs2[xkv0 * 4 + 7][2 * xr] = make_float2(pxb.w, pxb.w);
            wsn[xkv0 * 4 + 0][wcolbase] = pwa.x;
            wsn[xkv0 * 4 + 1][wcolbase] = pwa.y;
            wsn[xkv0 * 4 + 2][wcolbase] = pwa.z;
            wsn[xkv0 * 4 + 3][wcolbase] = pwa.w;
            wsn[xkv0 * 4 + 4][wcolbase] = pwb.x;
            wsn[xkv0 * 4 + 5][wcolbase] = pwb.y;
            wsn[xkv0 * 4 + 6][wcolbase] = pwb.z;
            wsn[xkv0 * 4 + 7][wcolbase] = pwb.w;
        }
        __syncthreads();

        // prefetch next tile (overlaps with compute below)
        if (kt + 1 < NT) {
            int k0 = (kt + 1) * BK;
            if (xok) {
                pxa = *(const float4*)(xrow + k0 + (xkv0 + 0) * 4);
                pxb = *(const float4*)(xrow + k0 + (xkv0 + 1) * 4);
            }
            pwa = *(const float4*)(wrow + k0 + (xkv0 + 0) * 4);
            pwb = *(const float4*)(wrow + k0 + (xkv0 + 1) * 4);
        }

#pragma unroll
        for (int k = 0; k < BK; k++) {
            union { float4 f; unsigned long long u[2]; } av[4], bv[2];
#pragma unroll
            for (int i2 = 0; i2 < 4; i2++)
                av[i2].f = *(const float4*)&xs2[k][2 * (ty * 8 + i2 * 2)];
#pragma unroll
            for (int p2 = 0; p2 < 2; p2++)
                bv[p2].f = *(const float4*)&wsn[k][p2 * 64 + tx * 4];
#pragma unroll
            for (int i = 0; i < 8; i++)
#pragma unroll
                for (int p = 0; p < 4; p++)
                    FMA2(acc2[i][p], av[i >> 1].u[i & 1], bv[p >> 1].u[p & 1], acc2[i][p]);
        }
        __syncthreads();
    }

    // ---- epilogue: bias, relu, write h, fused per-node gate params ----
    float bb[8], wdv[8], wsv[8];
#pragma unroll
    for (int j = 0; j < 8; j++) {
        bb[j]  = b1[tx * 8 + j];
        wdv[j] = gate_w[tx * 8 + j];
        wsv[j] = gate_w[HID + tx * 8 + j];
    }

#pragma unroll
    for (int i = 0; i < 8; i++) {
        int r = row0 + ty * 8 + i;   // NOTE: no break — shuffles below need all lanes
        float hv[8];
#pragma unroll
        for (int p = 0; p < 4; p++) {
            union { unsigned long long u; float2 f; } cv;
            cv.u = acc2[i][p];
            hv[2 * p + 0] = cv.f.x;
            hv[2 * p + 1] = cv.f.y;
        }
        float pd = 0.0f, ps = 0.0f;
#pragma unroll
        for (int j = 0; j < 8; j++) {
            float t = hv[j] + bb[j];
            hv[j] = t > 0.0f ? t : 0.0f;
            pd += hv[j] * wdv[j];
            ps += hv[j] * wsv[j];
        }
        // 16-lane reduction across tx (lanes with same ty share a row)
#pragma unroll
        for (int m = 1; m < 16; m <<= 1) {
            pd += __shfl_xor_sync(0xffffffffu, pd, m);
            ps += __shfl_xor_sync(0xffffffffu, ps, m);
        }
        if (r < Nn) {
            float* hp = g_h + (size_t)r * HID + tx * 8;
            *(float4*)(hp + 0) = make_float4(hv[0], hv[1], hv[2], hv[3]);
            *(float4*)(hp + 4) = make_float4(hv[4], hv[5], hv[6], hv[7]);
            if (tx == 0) {
                float d = (float)g_deg[r];
                if (d < 1.0f) d = 1.0f;
                g_p[r] = make_float4(pd, ps, rsqrtf(d), 0.0f);
            }
        }
    }
}

// ---------------------------------------------------------------
// fill CSR: one thread per edge; compute gate e, place (e, src) by dst bucket
__global__ void k_fill(const int* __restrict__ ei,
                       const float* __restrict__ gate_b, int E)
{
    int i = blockIdx.x * blockDim.x + threadIdx.x;
    if (i >= E) return;
    int s = ei[i];
    int d = ei[E + i];
    float4 pd = g_p[d];
    float4 ps = g_p[s];
    float g = tanhf(pd.x + ps.y + gate_b[0]);
    float e = g * pd.z * ps.z;
    int pos = g_off[d] + atomicAdd(&g_cur[d], 1);
    g_csr[pos] = make_float2(e, __int_as_float(s));
}

// ---------------------------------------------------------------
// aggregate: one warp per dst node; no atomics; fuse out = EPS*h + z.
// 4 edges per iteration with independent accumulators -> 4x gather MLP.
__global__ __launch_bounds__(256) void k_agg(float* __restrict__ out, int Nn)
{
    int node = blockIdx.x * 8 + (threadIdx.x >> 5);
    int lane = threadIdx.x & 31;
    if (node >= Nn) return;

    int beg = g_off[node];
    int end = beg + g_deg[node];

    float4 acc0 = make_float4(0.f, 0.f, 0.f, 0.f);
    float4 acc1 = make_float4(0.f, 0.f, 0.f, 0.f);
    float4 acc2 = make_float4(0.f, 0.f, 0.f, 0.f);
    float4 acc3 = make_float4(0.f, 0.f, 0.f, 0.f);

    int t = beg;
    for (; t + 3 < end; t += 4) {
        float2 c0 = g_csr[t];
        float2 c1 = g_csr[t + 1];
        float2 c2 = g_csr[t + 2];
        float2 c3 = g_csr[t + 3];
        float4 h0 = ((const float4*)(g_h + (size_t)__float_as_int(c0.y) * HID))[lane];
        float4 h1 = ((const float4*)(g_h + (size_t)__float_as_int(c1.y) * HID))[lane];
        float4 h2 = ((const float4*)(g_h + (size_t)__float_as_int(c2.y) * HID))[lane];
        float4 h3 = ((const float4*)(g_h + (size_t)__float_as_int(c3.y) * HID))[lane];
        acc0.x += h0.x * c0.x; acc0.y += h0.y * c0.x; acc0.z += h0.z * c0.x; acc0.w += h0.w * c0.x;
        acc1.x += h1.x * c1.x; acc1.y += h1.y * c1.x; acc1.z += h1.z * c1.x; acc1.w += h1.w * c1.x;
        acc2.x += h2.x * c2.x; acc2.y += h2.y * c2.x; acc2.z += h2.z * c2.x; acc2.w += h2.w * c2.x;
        acc3.x += h3.x * c3.x; acc3.y += h3.y * c3.x; acc3.z += h3.z * c3.x; acc3.w += h3.w * c3.x;
    }
    for (; t < end; t++) {
        float2 c0 = g_csr[t];
        float4 h0 = ((const float4*)(g_h + (size_t)__float_as_int(c0.y) * HID))[lane];
        acc0.x += h0.x * c0.x; acc0.y += h0.y * c0.x; acc0.z += h0.z * c0.x; acc0.w += h0.w * c0.x;
    }

    float4 mine = ((const float4*)(g_h + (size_t)node * HID))[lane];
    float4 o;
    o.x = EPS_C * mine.x + ((acc0.x + acc1.x) + (acc2.x + acc3.x));
    o.y = EPS_C * mine.y + ((acc0.y + acc1.y) + (acc2.y + acc3.y));
    o.z = EPS_C * mine.z + ((acc0.z + acc1.z) + (acc2.z + acc3.z));
    o.w = EPS_C * mine.w + ((acc0.w + acc1.w) + (acc2.w + acc3.w));
    ((float4*)(out + (size_t)node * HID))[lane] = o;
}

// ---------------------------------------------------------------
extern "C" void kernel_launch(void* const* d_in, const int* in_sizes, int n_in,
                              void* d_out, int out_size)
{
    const float* x      = (const float*)d_in[0];
    const int*   ei     = (const int*)d_in[1];
    const float* w1     = (const float*)d_in[2];
    const float* b1     = (const float*)d_in[3];
    const float* gate_w = (const float*)d_in[4];
    const float* gate_b = (const float*)d_in[5];
    float* out = (float*)d_out;

    int Nn = in_sizes[0] / IN_DIM;     // 100000
    int E  = in_sizes[1] / 2;          // 1600000
    int nb = (Nn + 255) / 256;         // scan blocks (391)

    // k_gemm kept as launch #4 (ncu -s 5 -c 1 captures launch #4).
    k_zero<<<(Nn + 255) / 256, 256>>>(Nn);                 // 1
    k_deg<<<(E + 255) / 256, 256>>>(ei + E, E);            // 2
    k_scan1<<<nb, 256>>>(Nn);                              // 3
    k_gemm<<<(Nn + 127) / 128, 256>>>(x, w1, b1, gate_w, Nn); // 4 <- profiled
    k_scan2<<<1, 512>>>(nb);                               // 5
    k_scan3<<<(Nn + 255) / 256, 256>>>(Nn);                // 6
    k_fill<<<(E + 255) / 256, 256>>>(ei, gate_b, E);       // 7
    k_agg<<<(Nn + 7) / 8, 256>>>(out, Nn);                 // 8
}

// round 8
// speedup vs baseline: 2.0164x; 1.4970x over previous
#include <cuda_runtime.h>
#include <cuda_bf16.h>
#include <math.h>
#include <stdint.h>

#define IN_DIM 256
#define HID    128
#define EPS_C  0.3f
#define MAXN   100000
#define MAXE   1600000

// -------- scratch (static device globals; no allocation) --------
__device__ float  g_h[(size_t)MAXN * HID];   // h = relu(x@w1.T+b1)
__device__ float  g_pd[MAXN];                // a_dst per node
__device__ float  g_ps[MAXN];                // a_src per node
__device__ float  g_norm[MAXN];              // rsqrt(max(deg,1))
__device__ int    g_deg[MAXN];
__device__ int    g_off[MAXN];
__device__ int    g_cur[MAXN];
__device__ int    g_bsum[512];
__device__ int    g_bscan[512];
__device__ float2 g_csr[MAXE];               // per-edge (e, src_bits) sorted by dst

// ---------------------------------------------------------------
__global__ void k_zero(int n) {
    int i = blockIdx.x * blockDim.x + threadIdx.x;
    if (i < n) { g_deg[i] = 0; g_cur[i] = 0; }
}

__global__ void k_deg(const int* __restrict__ dst, int E) {
    int i = blockIdx.x * blockDim.x + threadIdx.x;
    if (i < E) atomicAdd(&g_deg[dst[i]], 1);
}

// ---------------------------------------------------------------
__global__ void k_scan1(int n) {
    __shared__ int s[256];
    int t = threadIdx.x, i = blockIdx.x * 256 + t;
    int v = (i < n) ? g_deg[i] : 0;
    s[t] = v; __syncthreads();
#pragma unroll
    for (int o = 1; o < 256; o <<= 1) {
        int x = (t >= o) ? s[t - o] : 0;
        __syncthreads();
        s[t] += x;
        __syncthreads();
    }
    if (i < n) g_off[i] = s[t] - v;
    if (t == 255) g_bsum[blockIdx.x] = s[255];
}
__global__ void k_scan2(int nb) {
    __shared__ int s[512];
    int t = threadIdx.x;
    int v = (t < nb) ? g_bsum[t] : 0;
    s[t] = v; __syncthreads();
#pragma unroll
    for (int o = 1; o < 512; o <<= 1) {
        int x = (t >= o) ? s[t - o] : 0;
        __syncthreads();
        s[t] += x;
        __syncthreads();
    }
    if (t < nb) g_bscan[t] = s[t] - v;
}
__global__ void k_scan3(int n) {
    int i = blockIdx.x * blockDim.x + threadIdx.x;
    if (i < n) {
        g_off[i] += g_bscan[i >> 8];
        float d = (float)g_deg[i];
        if (d < 1.0f) d = 1.0f;
        g_norm[i] = rsqrtf(d);
    }
}

// ---------------------------------------------------------------
// tensor-core GEMM via mma.sync bf16 (3-term compensated)
// C[128 x 128] per block; K=256 in 8 chunks of 32.
// ---------------------------------------------------------------
#define LDSM_X4(r0, r1, r2, r3, a) \
    asm volatile("ldmatrix.sync.aligned.m8n8.x4.shared.b16 {%0,%1,%2,%3}, [%4];" \
                 : "=r"(r0), "=r"(r1), "=r"(r2), "=r"(r3) : "r"(a))
#define LDSM_X2(r0, r1, a) \
    asm volatile("ldmatrix.sync.aligned.m8n8.x2.shared.b16 {%0,%1}, [%2];" \
                 : "=r"(r0), "=r"(r1) : "r"(a))
#define MMA_BF16(d, a, b) \
    asm volatile("mma.sync.aligned.m16n8k16.row.col.f32.bf16.bf16.f32 " \
                 "{%0,%1,%2,%3}, {%4,%5,%6,%7}, {%8,%9}, {%0,%1,%2,%3};" \
                 : "+f"((d)[0]), "+f"((d)[1]), "+f"((d)[2]), "+f"((d)[3]) \
                 : "r"((a)[0]), "r"((a)[1]), "r"((a)[2]), "r"((a)[3]), \
                   "r"((b)[0]), "r"((b)[1]))

__device__ __forceinline__ uint32_t smem_u32(const void* p) {
    uint32_t a;
    asm("{ .reg .u64 t; cvta.to.shared.u64 t, %1; cvt.u32.u64 %0, t; }"
        : "=r"(a) : "l"(p));
    return a;
}
// byte offset of 16B-chunk c (0..3) of row r in a [128 x 64B] tile, XOR-swizzled
__device__ __forceinline__ uint32_t swz(int r, int c) {
    return (uint32_t)((r << 6) + ((c ^ ((r >> 1) & 3)) << 4));
}
__device__ __forceinline__ uint32_t pk(__nv_bfloat16 a, __nv_bfloat16 b) {
    __nv_bfloat162 t; t.x = a; t.y = b;
    return *(uint32_t*)&t;
}
// split 8 floats (two float4) into bf16 hi and lo 16B chunks
__device__ __forceinline__ void split8(float4 a, float4 b, uint4& hi, uint4& lo) {
    __nv_bfloat16 h0 = __float2bfloat16(a.x), h1 = __float2bfloat16(a.y);
    __nv_bfloat16 h2 = __float2bfloat16(a.z), h3 = __float2bfloat16(a.w);
    __nv_bfloat16 h4 = __float2bfloat16(b.x), h5 = __float2bfloat16(b.y);
    __nv_bfloat16 h6 = __float2bfloat16(b.z), h7 = __float2bfloat16(b.w);
    hi.x = pk(h0, h1); hi.y = pk(h2, h3); hi.z = pk(h4, h5); hi.w = pk(h6, h7);
    lo.x = pk(__float2bfloat16(a.x - __bfloat162float(h0)),
              __float2bfloat16(a.y - __bfloat162float(h1)));
    lo.y = pk(__float2bfloat16(a.z - __bfloat162float(h2)),
              __float2bfloat16(a.w - __bfloat162float(h3)));
    lo.z = pk(__float2bfloat16(b.x - __bfloat162float(h4)),
              __float2bfloat16(b.y - __bfloat162float(h5)));
    lo.w = pk(__float2bfloat16(b.z - __bfloat162float(h6)),
              __float2bfloat16(b.w - __bfloat162float(h7)));
}

__global__ __launch_bounds__(256) void k_gemm_mma(
    const float* __restrict__ x, const float* __restrict__ w1,
    const float* __restrict__ b1, const float* __restrict__ gate_w, int Nn)
{
    __shared__ __align__(16) uint8_t sAh[8192], sAl[8192], sBh[8192], sBl[8192];
    __shared__ float spd[128][2], sps[128][2], sbw[384];

    int tid = threadIdx.x, lane = tid & 31, wid = tid >> 5;
    int row0 = blockIdx.x * 128;
    int wm = wid & 3, wn = wid >> 2;
    int m0 = wm * 32, n0 = wn * 64;

    uint32_t bAh = smem_u32(sAh), bAl = smem_u32(sAl);
    uint32_t bBh = smem_u32(sBh), bBl = smem_u32(sBl);

    // producer mapping: each thread fills half a row per chunk
    int pr = tid >> 1, ph = tid & 1;
    const float* xp = x + (size_t)(row0 + pr) * IN_DIM;
    const float* wp = w1 + (size_t)pr * IN_DIM;
    bool xok = (row0 + pr) < Nn;

    float d[16][4];   // [mt*8+nt][4]
#pragma unroll
    for (int i = 0; i < 16; i++)
#pragma unroll
        for (int j = 0; j < 4; j++) d[i][j] = 0.0f;

    // ldmatrix address components (fixed per thread)
    int aRow = lane & 15;          // A: rows m + aRow
    int aCH  = lane >> 4;          // A: chunk high bit
    int bIdx = lane & 15;
    int bRow = bIdx & 7;           // B: rows n + bRow
    int bCH  = bIdx >> 3;          // B: chunk high bit

    for (int kc = 0; kc < 8; kc++) {
        int kb = kc * 32 + ph * 16;
        float4 v0 = make_float4(0.f, 0.f, 0.f, 0.f), v1 = v0, v2, v3;
        if (xok) {
            v0 = *(const float4*)(xp + kb);
            v1 = *(const float4*)(xp + kb + 4);
        }
        v2 = *(const float4*)(wp + kb);
        v3 = *(const float4*)(wp + kb + 4);
        float4 v0b = make_float4(0.f, 0.f, 0.f, 0.f), v1b = v0b, v2b, v3b;
        if (xok) {
            v0b = *(const float4*)(xp + kb + 8);
            v1b = *(const float4*)(xp + kb + 12);
        }
        v2b = *(const float4*)(wp + kb + 8);
        v3b = *(const float4*)(wp + kb + 12);

        uint4 hA0, lA0, hA1, lA1, hB0, lB0, hB1, lB1;
        split8(v0, v1, hA0, lA0);
        split8(v0b, v1b, hA1, lA1);
        split8(v2, v3, hB0, lB0);
        split8(v2b, v3b, hB1, lB1);

        uint32_t o0 = swz(pr, ph * 2), o1 = swz(pr, ph * 2 + 1);
        *(uint4*)(sAh + o0) = hA0;  *(uint4*)(sAh + o1) = hA1;
        *(uint4*)(sAl + o0) = lA0;  *(uint4*)(sAl + o1) = lA1;
        *(uint4*)(sBh + o0) = hB0;  *(uint4*)(sBh + o1) = hB1;
        *(uint4*)(sBl + o0) = lB0;  *(uint4*)(sBl + o1) = lB1;
        __syncthreads();

#pragma unroll
        for (int s = 0; s < 2; s++) {
            int ca = s * 2 + aCH;
            uint32_t oA0 = swz(m0 + aRow, ca);
            uint32_t oA1 = swz(m0 + 16 + aRow, ca);
            uint32_t ah0[4], al0[4], ah1[4], al1[4];
            LDSM_X4(ah0[0], ah0[1], ah0[2], ah0[3], bAh + oA0);
            LDSM_X4(al0[0], al0[1], al0[2], al0[3], bAl + oA0);
            LDSM_X4(ah1[0], ah1[1], ah1[2], ah1[3], bAh + oA1);
            LDSM_X4(al1[0], al1[1], al1[2], al1[3], bAl + oA1);
            int cb = s * 2 + bCH;
#pragma unroll
            for (int nt = 0; nt < 8; nt++) {
                uint32_t oB = swz(n0 + nt * 8 + bRow, cb);
                uint32_t bh[2], bl[2];
                LDSM_X2(bh[0], bh[1], bBh + oB);
                LDSM_X2(bl[0], bl[1], bBl + oB);
                MMA_BF16(d[nt], ah0, bh);
                MMA_BF16(d[nt], ah0, bl);
                MMA_BF16(d[nt], al0, bh);
                MMA_BF16(d[8 + nt], ah1, bh);
                MMA_BF16(d[8 + nt], ah1, bl);
                MMA_BF16(d[8 + nt], al1, bh);
            }
        }
        __syncthreads();
    }

    // ---- epilogue: bias + relu + write h + fused gate params ----
    if (tid < 128) {
        sbw[tid]       = b1[tid];
        sbw[128 + tid] = gate_w[tid];
        sbw[256 + tid] = gate_w[HID + tid];
    }
    __syncthreads();

    int qr = lane >> 2;   // 0..7
    int qc = lane & 3;    // col-pair index
    float ppd[4] = {0.f, 0.f, 0.f, 0.f};
    float pps[4] = {0.f, 0.f, 0.f, 0.f};
#pragma unroll
    for (int mt = 0; mt < 2; mt++) {
        int r1 = row0 + m0 + mt * 16 + qr;   // rows r1 and r1+8
#pragma unroll
        for (int nt = 0; nt < 8; nt++) {
            int c0 = n0 + nt * 8 + qc * 2;
            float bw0 = sbw[c0], bw1 = sbw[c0 + 1];
            float wd0 = sbw[128 + c0], wd1 = sbw[128 + c0 + 1];
            float ws0 = sbw[256 + c0], ws1 = sbw[256 + c0 + 1];
            float* dd = d[mt * 8 + nt];
            float h00 = dd[0] + bw0; h00 = h00 > 0.f ? h00 : 0.f;
            float h01 = dd[1] + bw1; h01 = h01 > 0.f ? h01 : 0.f;
            float h10 = dd[2] + bw0; h10 = h10 > 0.f ? h10 : 0.f;
            float h11 = dd[3] + bw1; h11 = h11 > 0.f ? h11 : 0.f;
            if (r1 < Nn)
                *(float2*)(g_h + (size_t)r1 * HID + c0) = make_float2(h00, h01);
            if (r1 + 8 < Nn)
                *(float2*)(g_h + (size_t)(r1 + 8) * HID + c0) = make_float2(h10, h11);
            ppd[mt * 2 + 0] += h00 * wd0 + h01 * wd1;
            ppd[mt * 2 + 1] += h10 * wd0 + h11 * wd1;
            pps[mt * 2 + 0] += h00 * ws0 + h01 * ws1;
            pps[mt * 2 + 1] += h10 * ws0 + h11 * ws1;
        }
    }
    // reduce over the 4 lanes holding the same rows (lanes 4a..4a+3)
#pragma unroll
    for (int m = 1; m < 4; m <<= 1) {
#pragma unroll
        for (int i = 0; i < 4; i++) {
            ppd[i] += __shfl_xor_sync(0xffffffffu, ppd[i], m);
            pps[i] += __shfl_xor_sync(0xffffffffu, pps[i], m);
        }
    }
    if (qc == 0) {
        // rows (relative): m0+qr, m0+8+qr, m0+16+qr, m0+24+qr
        spd[m0 + qr][wn]      = ppd[0];  sps[m0 + qr][wn]      = pps[0];
        spd[m0 + 8 + qr][wn]  = ppd[1];  sps[m0 + 8 + qr][wn]  = pps[1];
        spd[m0 + 16 + qr][wn] = ppd[2];  sps[m0 + 16 + qr][wn] = pps[2];
        spd[m0 + 24 + qr][wn] = ppd[3];  sps[m0 + 24 + qr][wn] = pps[3];
    }
    __syncthreads();
    if (tid < 128) {
        int gr = row0 + tid;
        if (gr < Nn) {
            g_pd[gr] = spd[tid][0] + spd[tid][1];
            g_ps[gr] = sps[tid][0] + sps[tid][1];
        }
    }
}

// ---------------------------------------------------------------
__global__ void k_fill(const int* __restrict__ ei,
                       const float* __restrict__ gate_b, int E)
{
    int i = blockIdx.x * blockDim.x + threadIdx.x;
    if (i >= E) return;
    int s = ei[i];
    int dn = ei[E + i];
    float g = tanhf(g_pd[dn] + g_ps[s] + gate_b[0]);
    float e = g * g_norm[dn] * g_norm[s];
    int pos = g_off[dn] + atomicAdd(&g_cur[dn], 1);
    g_csr[pos] = make_float2(e, __int_as_float(s));
}

// ---------------------------------------------------------------
__global__ __launch_bounds__(256) void k_agg(float* __restrict__ out, int Nn)
{
    int node = blockIdx.x * 8 + (threadIdx.x >> 5);
    int lane = threadIdx.x & 31;
    if (node >= Nn) return;

    int beg = g_off[node];
    int end = beg + g_deg[node];

    float4 acc0 = make_float4(0.f, 0.f, 0.f, 0.f);
    float4 acc1 = make_float4(0.f, 0.f, 0.f, 0.f);
    float4 acc2 = make_float4(0.f, 0.f, 0.f, 0.f);
    float4 acc3 = make_float4(0.f, 0.f, 0.f, 0.f);

    int t = beg;
    for (; t + 3 < end; t += 4) {
        float2 c0 = g_csr[t];
        float2 c1 = g_csr[t + 1];
        float2 c2 = g_csr[t + 2];
        float2 c3 = g_csr[t + 3];
        float4 h0 = ((const float4*)(g_h + (size_t)__float_as_int(c0.y) * HID))[lane];
        float4 h1 = ((const float4*)(g_h + (size_t)__float_as_int(c1.y) * HID))[lane];
        float4 h2 = ((const float4*)(g_h + (size_t)__float_as_int(c2.y) * HID))[lane];
        float4 h3 = ((const float4*)(g_h + (size_t)__float_as_int(c3.y) * HID))[lane];
        acc0.x += h0.x * c0.x; acc0.y += h0.y * c0.x; acc0.z += h0.z * c0.x; acc0.w += h0.w * c0.x;
        acc1.x += h1.x * c1.x; acc1.y += h1.y * c1.x; acc1.z += h1.z * c1.x; acc1.w += h1.w * c1.x;
        acc2.x += h2.x * c2.x; acc2.y += h2.y * c2.x; acc2.z += h2.z * c2.x; acc2.w += h2.w * c2.x;
        acc3.x += h3.x * c3.x; acc3.y += h3.y * c3.x; acc3.z += h3.z * c3.x; acc3.w += h3.w * c3.x;
    }
    for (; t < end; t++) {
        float2 c0 = g_csr[t];
        float4 h0 = ((const float4*)(g_h + (size_t)__float_as_int(c0.y) * HID))[lane];
        acc0.x += h0.x * c0.x; acc0.y += h0.y * c0.x; acc0.z += h0.z * c0.x; acc0.w += h0.w * c0.x;
    }

    float4 mine = ((const float4*)(g_h + (size_t)node * HID))[lane];
    float4 o;
    o.x = EPS_C * mine.x + ((acc0.x + acc1.x) + (acc2.x + acc3.x));
    o.y = EPS_C * mine.y + ((acc0.y + acc1.y) + (acc2.y + acc3.y));
    o.z = EPS_C * mine.z + ((acc0.z + acc1.z) + (acc2.z + acc3.z));
    o.w = EPS_C * mine.w + ((acc0.w + acc1.w) + (acc2.w + acc3.w));
    ((float4*)(out + (size_t)node * HID))[lane] = o;
}

// ---------------------------------------------------------------
extern "C" void kernel_launch(void* const* d_in, const int* in_sizes, int n_in,
                              void* d_out, int out_size)
{
    const float* x      = (const float*)d_in[0];
    const int*   ei     = (const int*)d_in[1];
    const float* w1     = (const float*)d_in[2];
    const float* b1     = (const float*)d_in[3];
    const float* gate_w = (const float*)d_in[4];
    const float* gate_b = (const float*)d_in[5];
    float* out = (float*)d_out;

    int Nn = in_sizes[0] / IN_DIM;     // 100000
    int E  = in_sizes[1] / 2;          // 1600000
    int nb = (Nn + 255) / 256;         // scan blocks

    // k_gemm_mma kept as launch #4 (ncu -s 5 -c 1 captures launch #4).
    k_zero<<<(Nn + 255) / 256, 256>>>(Nn);                        // 1
    k_deg<<<(E + 255) / 256, 256>>>(ei + E, E);                   // 2
    k_scan1<<<nb, 256>>>(Nn);                                     // 3
    k_gemm_mma<<<(Nn + 127) / 128, 256>>>(x, w1, b1, gate_w, Nn); // 4 <- profiled
    k_scan2<<<1, 512>>>(nb);                                      // 5
    k_scan3<<<(Nn + 255) / 256, 256>>>(Nn);                       // 6
    k_fill<<<(E + 255) / 256, 256>>>(ei, gate_b, E);              // 7
    k_agg<<<(Nn + 7) / 8, 256>>>(out, Nn);                        // 8
}